// round 6
// baseline (speedup 1.0000x reference)
#include <cuda_runtime.h>

// LSTM seq2seq: B=16384, S=T=64, I=4, M=16, H=64
// 128 CTAs x 256 threads. Thread = 2 gate rows x half-K.
// k-half partners are lanes l, l^16 of the same warp -> shuffle reduction (no smem partials).
// Cell0/cell1 software-pipelined across 32-col batch phases: 10 barriers/step.

#define SEQ 64
typedef unsigned long long ull;

__device__ __forceinline__ void fma2(ull& d, ull a, ull b) {
    asm("fma.rn.f32x2 %0, %1, %2, %0;" : "+l"(d) : "l"(a), "l"(b));
}
__device__ __forceinline__ ull addf2(ull a, ull b) {
    ull r; asm("add.rn.f32x2 %0, %1, %2;" : "=l"(r) : "l"(a), "l"(b)); return r;
}
__device__ __forceinline__ float2 unpk(ull v) {
    float2 r; asm("mov.b64 {%0,%1}, %2;" : "=f"(r.x), "=f"(r.y) : "l"(v)); return r;
}
__device__ __forceinline__ ull packf2(float x, float y) {
    ull r; asm("mov.b64 %0, {%1,%2};" : "=l"(r) : "f"(x), "f"(y)); return r;
}
__device__ __forceinline__ float fexp2a(float x) { float y; asm("ex2.approx.f32 %0, %1;" : "=f"(y) : "f"(x)); return y; }
__device__ __forceinline__ float frcpa (float x) { float y; asm("rcp.approx.f32 %0, %1;" : "=f"(y) : "f"(x)); return y; }
__device__ __forceinline__ float sig_f (float x) { return frcpa(1.0f + fexp2a(-1.4426950408889634f * x)); }
__device__ __forceinline__ float tanh_f(float x) { return 2.0f * frcpa(1.0f + fexp2a(-2.8853900817779268f * x)) - 1.0f; }

// smem float offsets
// ACT quad rows: [0..3]=MID(16), [4..19]=H1(64), [20..35]=H2(64); each quad row = 128 float4
#define OFF_ACT   0
#define OFF_C1    18432            // float4 [16][128] = 8192 floats
#define OFF_C2    26624
#define OFF_G     34816            // ull [2][128][33] finals = 16896 floats
#define OFF_X     51712            // float4 [128] = 512 floats
#define OFF_WOUT  52224            // 256
#define OFF_WIN   52480            // 64
#define OFF_BIN   52544            // 16
#define OFF_BOUT  52560            // 4
#define SMEM_FLOATS 52564

// Gate pass for one cell, one 32-col phase. Thread computes rows (rp, rp+128)
// over its k-half; shuffle-xor(16) folds the two k-halves; kh==0 lanes store finals.
template<int NQ>
__device__ __forceinline__ void gate_pass(
    const ulonglong2* __restrict__ base,   // this k-half's first activation quad
    const ull* __restrict__ w0, const ull* __restrict__ w1,
    ull bias0, ull bias1,                  // packed (bias,0) on kh==0 lanes, 0 on kh==1
    ull* __restrict__ Gc, int rp, int kh, int bbase)
{
#pragma unroll 1
    for (int b2 = 0; b2 < 32; ++b2) {
        const int b = bbase + b2;
        ull a00 = bias0, a01 = 0ull, a10 = bias1, a11 = 0ull;
#pragma unroll
        for (int q = 0; q < NQ; ++q) {
            ulonglong2 v = base[q * 128 + b];
            fma2(a00, w0[2*q],   v.x);
            fma2(a01, w0[2*q+1], v.y);
            fma2(a10, w1[2*q],   v.x);
            fma2(a11, w1[2*q+1], v.y);
        }
        float2 s0 = unpk(addf2(a00, a01));
        float2 s1 = unpk(addf2(a10, a11));
        ull mine = packf2(s0.x + s0.y, s1.x + s1.y);
        ull peer = __shfl_xor_sync(0xffffffffu, mine, 16);
        ull tot  = addf2(mine, peer);
        if (kh == 0) Gc[rp * 33 + b2] = tot;
    }
}

// Combine for one cell, one 32-col phase: 512 (quad,b2) items over 256 threads.
// Gc[u] = (i_u, g_u) final; Gc[u+64] = (f_u, o_u) final.
__device__ __forceinline__ void combine_cell(
    const ull* __restrict__ Gc, float4* __restrict__ Cq, float4* __restrict__ Hq,
    int tid, int bbase)
{
#pragma unroll
    for (int it = 0; it < 2; ++it) {
        const int item = tid + it * 256;
        const int q  = item >> 5;
        const int b2 = item & 31;
        const int b  = bbase + b2;
        float4 c = Cq[q * 128 + b];
        float4 h;
        float* cp = &c.x; float* hp = &h.x;
#pragma unroll
        for (int j = 0; j < 4; ++j) {
            const int u = q * 4 + j;
            float2 ig = unpk(Gc[u * 33 + b2]);
            float2 fo = unpk(Gc[(u + 64) * 33 + b2]);
            float cc = sig_f(fo.x) * cp[j] + sig_f(ig.x) * tanh_f(ig.y);
            cp[j] = cc;
            hp[j] = sig_f(fo.y) * tanh_f(cc);
        }
        Cq[q * 128 + b] = c;
        Hq[q * 128 + b] = h;
    }
}

__device__ __forceinline__ void load_weights(
    const float* Wih0, const float* Whh0, const float* b0v,
    const float* Wih1, const float* Whh1, const float* b1v,
    int rp, int kh,
    ull* wA0, ull* wA1, ull* wB0, ull* wB1,
    ull& bpA0, ull& bpA1, ull& bpB0, ull& bpB1)
{
    const int r0 = rp, r1 = rp + 128;
    const ull* xi0 = (const ull*)Wih0;   // [256][8]
    const ull* hh0 = (const ull*)Whh0;   // [256][32]
#pragma unroll
    for (int p = 0; p < 20; ++p) {
        const int kp = kh * 20 + p;
        wA0[p] = (kp < 8) ? xi0[r0 * 8 + kp] : hh0[r0 * 32 + (kp - 8)];
        wA1[p] = (kp < 8) ? xi0[r1 * 8 + kp] : hh0[r1 * 32 + (kp - 8)];
    }
    const ull* c1 = kh ? (const ull*)Whh1 : (const ull*)Wih1;  // [256][32]
#pragma unroll
    for (int p = 0; p < 32; ++p) { wB0[p] = c1[r0 * 32 + p]; wB1[p] = c1[r1 * 32 + p]; }
    if (kh == 0) {
        bpA0 = packf2(b0v[r0], 0.f); bpA1 = packf2(b0v[r1], 0.f);
        bpB0 = packf2(b1v[r0], 0.f); bpB1 = packf2(b1v[r1], 0.f);
    } else {
        bpA0 = 0ull; bpA1 = 0ull; bpB0 = 0ull; bpB1 = 0ull;
    }
}

// mid = W_in @ x + b_in for one batch column, quad layout rows 0..3
__device__ __forceinline__ void mid_store(float4 x, int b, float* sm)
{
    const float* WIN = sm + OFF_WIN;
    const float* BIN = sm + OFF_BIN;
    float4* MQ = (float4*)(sm + OFF_ACT);
#pragma unroll
    for (int g = 0; g < 4; ++g) {
        float4 v;
        float* vp = &v.x;
#pragma unroll
        for (int j = 0; j < 4; ++j) {
            const int m = g * 4 + j;
            vp[j] = BIN[m] + WIN[m*4]*x.x + WIN[m*4+1]*x.y + WIN[m*4+2]*x.z + WIN[m*4+3]*x.w;
        }
        MQ[g * 128 + b] = v;
    }
}

// One full timestep: cell0/cell1 pipelined across 5 phase-iterations.
__device__ __forceinline__ void run_step(
    const ull* wA0, const ull* wA1, const ull* wB0, const ull* wB1,
    ull bpA0, ull bpA1, ull bpB0, ull bpB1,
    float* sm, int tid, int rp, int kh)
{
    ulonglong2* ACTq = (ulonglong2*)(sm + OFF_ACT);
    const ulonglong2* base0 = ACTq + kh * 10 * 128;        // cell0 K: quads [0..19]
    const ulonglong2* base1 = ACTq + (4 + kh * 16) * 128;  // cell1 K: quads [4..35]
    ull* G0 = (ull*)(sm + OFF_G);
    ull* G1 = G0 + 128 * 33;
    float4* C1q = (float4*)(sm + OFF_C1);
    float4* C2q = (float4*)(sm + OFF_C2);
    float4* H1q = (float4*)(sm + OFF_ACT) + 4 * 128;
    float4* H2q = (float4*)(sm + OFF_ACT) + 20 * 128;

#pragma unroll 1
    for (int p = 0; p < 5; ++p) {
        if (p < 4) gate_pass<10>(base0, wA0, wA1, bpA0, bpA1, G0, rp, kh, p * 32);
        if (p > 0) gate_pass<16>(base1, wB0, wB1, bpB0, bpB1, G1, rp, kh, (p - 1) * 32);
        __syncthreads();
        if (p < 4) combine_cell(G0, C1q, H1q, tid, p * 32);
        if (p > 0) combine_cell(G1, C2q, H2q, tid, (p - 1) * 32);
        __syncthreads();
    }
}

__global__ void __launch_bounds__(256, 1)
lstm_seq2seq_kernel(
    const float4* __restrict__ src4,   const float4* __restrict__ trg4,
    const float*  __restrict__ W_in,   const float*  __restrict__ b_in,
    const float*  __restrict__ eWih0,  const float*  __restrict__ eWhh0, const float* __restrict__ eb0,
    const float*  __restrict__ eWih1,  const float*  __restrict__ eWhh1, const float* __restrict__ eb1,
    const float*  __restrict__ dWih0,  const float*  __restrict__ dWhh0, const float* __restrict__ db0,
    const float*  __restrict__ dWih1,  const float*  __restrict__ dWhh1, const float* __restrict__ db1,
    const float*  __restrict__ W_out,  const float*  __restrict__ b_out,
    float4*       __restrict__ out4)
{
    extern __shared__ float sm[];
    const int tid  = threadIdx.x;
    const int warp = tid >> 5;
    const int lane = tid & 31;
    const int kh   = lane >> 4;                // k-half partners: lane ^ 16
    const int rp   = warp * 16 + (lane & 15);  // row-pair 0..127 -> rows rp, rp+128

    // consts
    if (tid < 64)  sm[OFF_WIN  + tid] = W_in[tid];
    if (tid < 256) sm[OFF_WOUT + tid] = W_out[tid];
    if (tid < 16)  sm[OFF_BIN  + tid] = b_in[tid];
    if (tid < 4)   sm[OFF_BOUT + tid] = b_out[tid];
    // zero H1,H2 (ACT quads 4..35) and C1,C2
    for (int i = tid; i < 16384; i += 256) sm[OFF_ACT + 2048 + i] = 0.f;
    for (int i = tid; i < 16384; i += 256) sm[OFF_C1 + i] = 0.f;
    __syncthreads();

    ull wA0[20], wA1[20], wB0[32], wB1[32];
    ull bpA0, bpA1, bpB0, bpB1;
    load_weights(eWih0, eWhh0, eb0, eWih1, eWhh1, eb1, rp, kh,
                 wA0, wA1, wB0, wB1, bpA0, bpA1, bpB0, bpB1);

    const size_t bg = (size_t)blockIdx.x * 128 + (tid & 127);

    // ================= ENCODER =================
    float4 xcur, xnext;
    if (tid < 128) xcur = __ldg(src4 + bg * SEQ);
    for (int t = 0; t < SEQ; ++t) {
        if (tid < 128) {
            mid_store(xcur, tid, sm);
            if (t + 1 < SEQ) xnext = __ldg(src4 + bg * SEQ + t + 1);
        }
        __syncthreads();
        run_step(wA0, wA1, wB0, wB1, bpA0, bpA1, bpB0, bpB1, sm, tid, rp, kh);
        xcur = xnext;
    }

    // reload decoder weights
    load_weights(dWih0, dWhh0, db0, dWih1, dWhh1, db1, rp, kh,
                 wA0, wA1, wB0, wB1, bpA0, bpA1, bpB0, bpB1);

    float4* Xs = (float4*)(sm + OFF_X);
    if (tid < 128) Xs[tid] = __ldg(trg4 + bg * SEQ);   // x0 = trg[:,0]
    __syncthreads();

    // ================= DECODER =================
    for (int t = 0; t < SEQ; ++t) {
        float4 tg;
        if (tid < 128) {
            mid_store(Xs[tid], tid, sm);
            tg = __ldg(trg4 + bg * SEQ + t);
        }
        __syncthreads();
        run_step(wA0, wA1, wB0, wB1, bpA0, bpA1, bpB0, bpB1, sm, tid, rp, kh);
        if (tid < 128) {
            // pred = W_out @ h2 + b_out
            const float* WOUT = sm + OFF_WOUT;
            const float4* H2q = (const float4*)(sm + OFF_ACT) + 20 * 128;
            float p0 = sm[OFF_BOUT+0], p1 = sm[OFF_BOUT+1], p2 = sm[OFF_BOUT+2], p3 = sm[OFF_BOUT+3];
#pragma unroll
            for (int q = 0; q < 16; ++q) {
                float4 h = H2q[q * 128 + tid];
                p0 += WOUT[0*64+q*4]*h.x + WOUT[0*64+q*4+1]*h.y + WOUT[0*64+q*4+2]*h.z + WOUT[0*64+q*4+3]*h.w;
                p1 += WOUT[1*64+q*4]*h.x + WOUT[1*64+q*4+1]*h.y + WOUT[1*64+q*4+2]*h.z + WOUT[1*64+q*4+3]*h.w;
                p2 += WOUT[2*64+q*4]*h.x + WOUT[2*64+q*4+1]*h.y + WOUT[2*64+q*4+2]*h.z + WOUT[2*64+q*4+3]*h.w;
                p3 += WOUT[3*64+q*4]*h.x + WOUT[3*64+q*4+1]*h.y + WOUT[3*64+q*4+2]*h.z + WOUT[3*64+q*4+3]*h.w;
            }
            float4 xo;
            xo.x = p0 + tg.x; xo.y = p1 + tg.y; xo.z = p2 + tg.z; xo.w = p3 + tg.w;
            out4[bg * SEQ + t] = xo;
            Xs[tid] = xo;
        }
        __syncthreads();
    }
}

extern "C" void kernel_launch(void* const* d_in, const int* in_sizes, int n_in,
                              void* d_out, int out_size)
{
    (void)in_sizes; (void)n_in; (void)out_size;
    const float4* src   = (const float4*)d_in[0];
    const float4* trg   = (const float4*)d_in[1];
    const float*  W_in  = (const float*)d_in[2];
    const float*  b_in  = (const float*)d_in[3];
    const float*  eWih0 = (const float*)d_in[4];
    const float*  eWhh0 = (const float*)d_in[5];
    const float*  eb0   = (const float*)d_in[6];
    const float*  eWih1 = (const float*)d_in[7];
    const float*  eWhh1 = (const float*)d_in[8];
    const float*  eb1   = (const float*)d_in[9];
    const float*  dWih0 = (const float*)d_in[10];
    const float*  dWhh0 = (const float*)d_in[11];
    const float*  db0   = (const float*)d_in[12];
    const float*  dWih1 = (const float*)d_in[13];
    const float*  dWhh1 = (const float*)d_in[14];
    const float*  db1   = (const float*)d_in[15];
    const float*  W_out = (const float*)d_in[16];
    const float*  b_out = (const float*)d_in[17];
    float4* out = (float4*)d_out;

    const size_t smem_bytes = (size_t)SMEM_FLOATS * sizeof(float); // 210,256 B
    cudaFuncSetAttribute(lstm_seq2seq_kernel,
                         cudaFuncAttributeMaxDynamicSharedMemorySize, (int)smem_bytes);

    lstm_seq2seq_kernel<<<128, 256, smem_bytes>>>(
        src, trg, W_in, b_in,
        eWih0, eWhh0, eb0, eWih1, eWhh1, eb1,
        dWih0, dWhh0, db0, dWih1, dWhh1, db1,
        W_out, b_out, out);
}

// round 7
// speedup vs baseline: 1.0054x; 1.0054x over previous
#include <cuda_runtime.h>

// LSTM seq2seq: B=16384, S=T=64, I=4, M=16, H=64
// 128 CTAs x 256 threads. Thread = 2 gate rows x half-K.
// k-half partners are lanes l, l^16 of the same warp -> shuffle reduction (no smem partials).
// Cell0/cell1 software-pipelined across 32-col batch phases: 10 barriers/step.

#define SEQ 64
typedef unsigned long long ull;

__device__ __forceinline__ void fma2(ull& d, ull a, ull b) {
    asm("fma.rn.f32x2 %0, %1, %2, %0;" : "+l"(d) : "l"(a), "l"(b));
}
__device__ __forceinline__ ull addf2(ull a, ull b) {
    ull r; asm("add.rn.f32x2 %0, %1, %2;" : "=l"(r) : "l"(a), "l"(b)); return r;
}
__device__ __forceinline__ float2 unpk(ull v) {
    float2 r; asm("mov.b64 {%0,%1}, %2;" : "=f"(r.x), "=f"(r.y) : "l"(v)); return r;
}
__device__ __forceinline__ ull packf2(float x, float y) {
    ull r; asm("mov.b64 %0, {%1,%2};" : "=l"(r) : "f"(x), "f"(y)); return r;
}
__device__ __forceinline__ float fexp2a(float x) { float y; asm("ex2.approx.f32 %0, %1;" : "=f"(y) : "f"(x)); return y; }
__device__ __forceinline__ float frcpa (float x) { float y; asm("rcp.approx.f32 %0, %1;" : "=f"(y) : "f"(x)); return y; }
__device__ __forceinline__ float sig_f (float x) { return frcpa(1.0f + fexp2a(-1.4426950408889634f * x)); }
__device__ __forceinline__ float tanh_f(float x) { return 2.0f * frcpa(1.0f + fexp2a(-2.8853900817779268f * x)) - 1.0f; }

// smem float offsets
// ACT quad rows: [0..3]=MID(16), [4..19]=H1(64), [20..35]=H2(64); each quad row = 128 float4
#define OFF_ACT   0
#define OFF_C1    18432            // float4 [16][128] = 8192 floats
#define OFF_C2    26624
#define OFF_G     34816            // ull [2][128][33] finals = 16896 floats
#define OFF_X     51712            // float4 [128] = 512 floats
#define OFF_WOUT  52224            // 256
#define OFF_WIN   52480            // 64
#define OFF_BIN   52544            // 16
#define OFF_BOUT  52560            // 4
#define SMEM_FLOATS 52564

// Gate pass for one cell, one 32-col phase. Thread computes rows (rp, rp+128)
// over its k-half; shuffle-xor(16) folds the two k-halves; kh==0 lanes store finals.
template<int NQ>
__device__ __forceinline__ void gate_pass(
    const ulonglong2* __restrict__ base,   // this k-half's first activation quad
    const ull* __restrict__ w0, const ull* __restrict__ w1,
    ull bias0, ull bias1,                  // packed (bias,0) on kh==0 lanes, 0 on kh==1
    ull* __restrict__ Gc, int rp, int kh, int bbase)
{
#pragma unroll 1
    for (int b2 = 0; b2 < 32; ++b2) {
        const int b = bbase + b2;
        ull a00 = bias0, a01 = 0ull, a10 = bias1, a11 = 0ull;
#pragma unroll
        for (int q = 0; q < NQ; ++q) {
            ulonglong2 v = base[q * 128 + b];
            fma2(a00, w0[2*q],   v.x);
            fma2(a01, w0[2*q+1], v.y);
            fma2(a10, w1[2*q],   v.x);
            fma2(a11, w1[2*q+1], v.y);
        }
        float2 s0 = unpk(addf2(a00, a01));
        float2 s1 = unpk(addf2(a10, a11));
        ull mine = packf2(s0.x + s0.y, s1.x + s1.y);
        ull peer = __shfl_xor_sync(0xffffffffu, mine, 16);
        ull tot  = addf2(mine, peer);
        if (kh == 0) Gc[rp * 33 + b2] = tot;
    }
}

// Combine for one cell, one 32-col phase: 512 (quad,b2) items over 256 threads.
// Gc[u] = (i_u, g_u) final; Gc[u+64] = (f_u, o_u) final.
__device__ __forceinline__ void combine_cell(
    const ull* __restrict__ Gc, float4* __restrict__ Cq, float4* __restrict__ Hq,
    int tid, int bbase)
{
#pragma unroll
    for (int it = 0; it < 2; ++it) {
        const int item = tid + it * 256;
        const int q  = item >> 5;
        const int b2 = item & 31;
        const int b  = bbase + b2;
        float4 c = Cq[q * 128 + b];
        float4 h;
        float* cp = &c.x; float* hp = &h.x;
#pragma unroll
        for (int j = 0; j < 4; ++j) {
            const int u = q * 4 + j;
            float2 ig = unpk(Gc[u * 33 + b2]);
            float2 fo = unpk(Gc[(u + 64) * 33 + b2]);
            float cc = sig_f(fo.x) * cp[j] + sig_f(ig.x) * tanh_f(ig.y);
            cp[j] = cc;
            hp[j] = sig_f(fo.y) * tanh_f(cc);
        }
        Cq[q * 128 + b] = c;
        Hq[q * 128 + b] = h;
    }
}

__device__ __forceinline__ void load_weights(
    const float* Wih0, const float* Whh0, const float* b0v,
    const float* Wih1, const float* Whh1, const float* b1v,
    int rp, int kh,
    ull* wA0, ull* wA1, ull* wB0, ull* wB1,
    ull& bpA0, ull& bpA1, ull& bpB0, ull& bpB1)
{
    const int r0 = rp, r1 = rp + 128;
    const ull* xi0 = (const ull*)Wih0;   // [256][8]
    const ull* hh0 = (const ull*)Whh0;   // [256][32]
#pragma unroll
    for (int p = 0; p < 20; ++p) {
        const int kp = kh * 20 + p;
        wA0[p] = (kp < 8) ? xi0[r0 * 8 + kp] : hh0[r0 * 32 + (kp - 8)];
        wA1[p] = (kp < 8) ? xi0[r1 * 8 + kp] : hh0[r1 * 32 + (kp - 8)];
    }
    const ull* c1 = kh ? (const ull*)Whh1 : (const ull*)Wih1;  // [256][32]
#pragma unroll
    for (int p = 0; p < 32; ++p) { wB0[p] = c1[r0 * 32 + p]; wB1[p] = c1[r1 * 32 + p]; }
    if (kh == 0) {
        bpA0 = packf2(b0v[r0], 0.f); bpA1 = packf2(b0v[r1], 0.f);
        bpB0 = packf2(b1v[r0], 0.f); bpB1 = packf2(b1v[r1], 0.f);
    } else {
        bpA0 = 0ull; bpA1 = 0ull; bpB0 = 0ull; bpB1 = 0ull;
    }
}

// mid = W_in @ x + b_in for one batch column, quad layout rows 0..3
__device__ __forceinline__ void mid_store(float4 x, int b, float* sm)
{
    const float* WIN = sm + OFF_WIN;
    const float* BIN = sm + OFF_BIN;
    float4* MQ = (float4*)(sm + OFF_ACT);
#pragma unroll
    for (int g = 0; g < 4; ++g) {
        float4 v;
        float* vp = &v.x;
#pragma unroll
        for (int j = 0; j < 4; ++j) {
            const int m = g * 4 + j;
            vp[j] = BIN[m] + WIN[m*4]*x.x + WIN[m*4+1]*x.y + WIN[m*4+2]*x.z + WIN[m*4+3]*x.w;
        }
        MQ[g * 128 + b] = v;
    }
}

// One full timestep: cell0/cell1 pipelined across 5 phase-iterations.
__device__ __forceinline__ void run_step(
    const ull* wA0, const ull* wA1, const ull* wB0, const ull* wB1,
    ull bpA0, ull bpA1, ull bpB0, ull bpB1,
    float* sm, int tid, int rp, int kh)
{
    ulonglong2* ACTq = (ulonglong2*)(sm + OFF_ACT);
    const ulonglong2* base0 = ACTq + kh * 10 * 128;        // cell0 K: quads [0..19]
    const ulonglong2* base1 = ACTq + (4 + kh * 16) * 128;  // cell1 K: quads [4..35]
    ull* G0 = (ull*)(sm + OFF_G);
    ull* G1 = G0 + 128 * 33;
    float4* C1q = (float4*)(sm + OFF_C1);
    float4* C2q = (float4*)(sm + OFF_C2);
    float4* H1q = (float4*)(sm + OFF_ACT) + 4 * 128;
    float4* H2q = (float4*)(sm + OFF_ACT) + 20 * 128;

#pragma unroll 1
    for (int p = 0; p < 5; ++p) {
        if (p < 4) gate_pass<10>(base0, wA0, wA1, bpA0, bpA1, G0, rp, kh, p * 32);
        if (p > 0) gate_pass<16>(base1, wB0, wB1, bpB0, bpB1, G1, rp, kh, (p - 1) * 32);
        __syncthreads();
        if (p < 4) combine_cell(G0, C1q, H1q, tid, p * 32);
        if (p > 0) combine_cell(G1, C2q, H2q, tid, (p - 1) * 32);
        __syncthreads();
    }
}

__global__ void __launch_bounds__(256, 1)
lstm_seq2seq_kernel(
    const float4* __restrict__ src4,   const float4* __restrict__ trg4,
    const float*  __restrict__ W_in,   const float*  __restrict__ b_in,
    const float*  __restrict__ eWih0,  const float*  __restrict__ eWhh0, const float* __restrict__ eb0,
    const float*  __restrict__ eWih1,  const float*  __restrict__ eWhh1, const float* __restrict__ eb1,
    const float*  __restrict__ dWih0,  const float*  __restrict__ dWhh0, const float* __restrict__ db0,
    const float*  __restrict__ dWih1,  const float*  __restrict__ dWhh1, const float* __restrict__ db1,
    const float*  __restrict__ W_out,  const float*  __restrict__ b_out,
    float4*       __restrict__ out4)
{
    extern __shared__ float sm[];
    const int tid  = threadIdx.x;
    const int warp = tid >> 5;
    const int lane = tid & 31;
    const int kh   = lane >> 4;                // k-half partners: lane ^ 16
    const int rp   = warp * 16 + (lane & 15);  // row-pair 0..127 -> rows rp, rp+128

    // consts
    if (tid < 64)  sm[OFF_WIN  + tid] = W_in[tid];
    if (tid < 256) sm[OFF_WOUT + tid] = W_out[tid];
    if (tid < 16)  sm[OFF_BIN  + tid] = b_in[tid];
    if (tid < 4)   sm[OFF_BOUT + tid] = b_out[tid];
    // zero H1,H2 (ACT quads 4..35) and C1,C2
    for (int i = tid; i < 16384; i += 256) sm[OFF_ACT + 2048 + i] = 0.f;
    for (int i = tid; i < 16384; i += 256) sm[OFF_C1 + i] = 0.f;
    __syncthreads();

    ull wA0[20], wA1[20], wB0[32], wB1[32];
    ull bpA0, bpA1, bpB0, bpB1;
    load_weights(eWih0, eWhh0, eb0, eWih1, eWhh1, eb1, rp, kh,
                 wA0, wA1, wB0, wB1, bpA0, bpA1, bpB0, bpB1);

    const size_t bg = (size_t)blockIdx.x * 128 + (tid & 127);

    // ================= ENCODER =================
    float4 xcur, xnext;
    if (tid < 128) xcur = __ldg(src4 + bg * SEQ);
    for (int t = 0; t < SEQ; ++t) {
        if (tid < 128) {
            mid_store(xcur, tid, sm);
            if (t + 1 < SEQ) xnext = __ldg(src4 + bg * SEQ + t + 1);
        }
        __syncthreads();
        run_step(wA0, wA1, wB0, wB1, bpA0, bpA1, bpB0, bpB1, sm, tid, rp, kh);
        xcur = xnext;
    }

    // reload decoder weights
    load_weights(dWih0, dWhh0, db0, dWih1, dWhh1, db1, rp, kh,
                 wA0, wA1, wB0, wB1, bpA0, bpA1, bpB0, bpB1);

    float4* Xs = (float4*)(sm + OFF_X);
    if (tid < 128) Xs[tid] = __ldg(trg4 + bg * SEQ);   // x0 = trg[:,0]
    __syncthreads();

    // ================= DECODER =================
    for (int t = 0; t < SEQ; ++t) {
        float4 tg;
        if (tid < 128) {
            mid_store(Xs[tid], tid, sm);
            tg = __ldg(trg4 + bg * SEQ + t);
        }
        __syncthreads();
        run_step(wA0, wA1, wB0, wB1, bpA0, bpA1, bpB0, bpB1, sm, tid, rp, kh);
        if (tid < 128) {
            // pred = W_out @ h2 + b_out
            const float* WOUT = sm + OFF_WOUT;
            const float4* H2q = (const float4*)(sm + OFF_ACT) + 20 * 128;
            float p0 = sm[OFF_BOUT+0], p1 = sm[OFF_BOUT+1], p2 = sm[OFF_BOUT+2], p3 = sm[OFF_BOUT+3];
#pragma unroll
            for (int q = 0; q < 16; ++q) {
                float4 h = H2q[q * 128 + tid];
                p0 += WOUT[0*64+q*4]*h.x + WOUT[0*64+q*4+1]*h.y + WOUT[0*64+q*4+2]*h.z + WOUT[0*64+q*4+3]*h.w;
                p1 += WOUT[1*64+q*4]*h.x + WOUT[1*64+q*4+1]*h.y + WOUT[1*64+q*4+2]*h.z + WOUT[1*64+q*4+3]*h.w;
                p2 += WOUT[2*64+q*4]*h.x + WOUT[2*64+q*4+1]*h.y + WOUT[2*64+q*4+2]*h.z + WOUT[2*64+q*4+3]*h.w;
                p3 += WOUT[3*64+q*4]*h.x + WOUT[3*64+q*4+1]*h.y + WOUT[3*64+q*4+2]*h.z + WOUT[3*64+q*4+3]*h.w;
            }
            float4 xo;
            xo.x = p0 + tg.x; xo.y = p1 + tg.y; xo.z = p2 + tg.z; xo.w = p3 + tg.w;
            out4[bg * SEQ + t] = xo;
            Xs[tid] = xo;
        }
        __syncthreads();
    }
}

extern "C" void kernel_launch(void* const* d_in, const int* in_sizes, int n_in,
                              void* d_out, int out_size)
{
    (void)in_sizes; (void)n_in; (void)out_size;
    const float4* src   = (const float4*)d_in[0];
    const float4* trg   = (const float4*)d_in[1];
    const float*  W_in  = (const float*)d_in[2];
    const float*  b_in  = (const float*)d_in[3];
    const float*  eWih0 = (const float*)d_in[4];
    const float*  eWhh0 = (const float*)d_in[5];
    const float*  eb0   = (const float*)d_in[6];
    const float*  eWih1 = (const float*)d_in[7];
    const float*  eWhh1 = (const float*)d_in[8];
    const float*  eb1   = (const float*)d_in[9];
    const float*  dWih0 = (const float*)d_in[10];
    const float*  dWhh0 = (const float*)d_in[11];
    const float*  db0   = (const float*)d_in[12];
    const float*  dWih1 = (const float*)d_in[13];
    const float*  dWhh1 = (const float*)d_in[14];
    const float*  db1   = (const float*)d_in[15];
    const float*  W_out = (const float*)d_in[16];
    const float*  b_out = (const float*)d_in[17];
    float4* out = (float4*)d_out;

    const size_t smem_bytes = (size_t)SMEM_FLOATS * sizeof(float); // 210,256 B
    cudaFuncSetAttribute(lstm_seq2seq_kernel,
                         cudaFuncAttributeMaxDynamicSharedMemorySize, (int)smem_bytes);

    lstm_seq2seq_kernel<<<128, 256, smem_bytes>>>(
        src, trg, W_in, b_in,
        eWih0, eWhh0, eb0, eWih1, eWhh1, eb1,
        dWih0, dWhh0, db0, dWih1, dWhh1, db1,
        W_out, b_out, out);
}

// round 10
// speedup vs baseline: 1.0930x; 1.0871x over previous
#include <cuda_runtime.h>

// LSTM seq2seq: B=16384, S=T=64, I=4, M=16, H=64
// 128 CTAs x 512 threads (16 warps/SM). Thread = 1 gate row x half-K.
// W_in folded into cell0 (gates0 = (Wih0@W_in)@x + Whh0@h1 + b0 + Wih0@b_in).
// k-half partners = lanes l, l^16 -> shuffle reduction. Col-pair gate loop.
// Activation quad rows padded to 129 float4 so the two half-warp broadcast
// addresses never bank-conflict.

#define SEQ 64
typedef unsigned long long ull;

__device__ __forceinline__ void fma2(ull& d, ull a, ull b) {
    asm("fma.rn.f32x2 %0, %1, %2, %0;" : "+l"(d) : "l"(a), "l"(b));
}
__device__ __forceinline__ ull addf2(ull a, ull b) {
    ull r; asm("add.rn.f32x2 %0, %1, %2;" : "=l"(r) : "l"(a), "l"(b)); return r;
}
__device__ __forceinline__ float2 unpk(ull v) {
    float2 r; asm("mov.b64 {%0,%1}, %2;" : "=f"(r.x), "=f"(r.y) : "l"(v)); return r;
}
__device__ __forceinline__ ull packf2(float x, float y) {
    ull r; asm("mov.b64 %0, {%1,%2};" : "=l"(r) : "f"(x), "f"(y)); return r;
}
__device__ __forceinline__ float fexp2a(float x) { float y; asm("ex2.approx.f32 %0, %1;" : "=f"(y) : "f"(x)); return y; }
__device__ __forceinline__ float frcpa (float x) { float y; asm("rcp.approx.f32 %0, %1;" : "=f"(y) : "f"(x)); return y; }
__device__ __forceinline__ float sig_f (float x) { return frcpa(1.0f + fexp2a(-1.4426950408889634f * x)); }
__device__ __forceinline__ float tanh_f(float x) { return 2.0f * frcpa(1.0f + fexp2a(-2.8853900817779268f * x)) - 1.0f; }

// ACT: 34 quad rows x 129 float4 (stride pad). row0=X, rows1..16=H1, row17=ZERO, rows18..33=H2
#define ACT_STRIDE 129
#define ROW_X     0
#define ROW_H1    1
#define ROW_ZERO  17
#define ROW_H2    18
// smem float offsets
#define OFF_ACT   0                       // 34*129*4 = 17544 floats
#define OFF_C1    17544                   // 64x128 = 8192
#define OFF_C2    25736                   // 8192
#define OFF_G0    33928                   // 256 rows x 17 ull = 8704 floats
#define OFF_G1    42632                   // 8704
#define OFF_WOUT  51336                   // 256
#define OFF_BOUT  51592                   // 4
#define SMEM_FLOATS 51596                 // 206,384 B
#define G_STRIDE  17                      // ull per gate row

// Gate pass: thread computes row rr over its k-half for 32 cols (16 col-pairs).
template<int NQ>
__device__ __forceinline__ void gate_pass(
    const float4* __restrict__ base, const ull* __restrict__ w, ull bias2,
    ull* __restrict__ Gc, int rr, int kh, int bbase)
{
#pragma unroll 1
    for (int cp = 0; cp < 16; ++cp) {
        const int b = bbase + 2 * cp;
        ull a0x = 0ull, a0y = 0ull, a1x = 0ull, a1y = 0ull;
#pragma unroll
        for (int q = 0; q < NQ; ++q) {
            ulonglong2 v0 = *(const ulonglong2*)(base + q * ACT_STRIDE + b);
            ulonglong2 v1 = *(const ulonglong2*)(base + q * ACT_STRIDE + b + 1);
            fma2(a0x, w[2*q],   v0.x);
            fma2(a0y, w[2*q+1], v0.y);
            fma2(a1x, w[2*q],   v1.x);
            fma2(a1y, w[2*q+1], v1.y);
        }
        float2 s0 = unpk(addf2(a0x, a0y));
        float2 s1 = unpk(addf2(a1x, a1y));
        ull mine = packf2(s0.x + s0.y, s1.x + s1.y);
        ull tot  = addf2(mine, __shfl_xor_sync(0xffffffffu, mine, 16));
        if (kh == 0) Gc[rr * G_STRIDE + cp] = addf2(tot, bias2);
    }
}

// Combine one cell for 32 cols: thread = 2 units x 1 col-pair (512 items).
__device__ __forceinline__ void combine_cell(
    const ull* __restrict__ Gc, float* __restrict__ C, float* __restrict__ ACTf,
    int hrow, int tid, int bbase)
{
    const int u2 = tid >> 4;          // 0..31
    const int cp = tid & 15;
    const int c0 = bbase + 2 * cp;
#pragma unroll
    for (int j = 0; j < 2; ++j) {
        const int u = u2 * 2 + j;
        float2 gi = unpk(Gc[u * G_STRIDE + cp]);
        float2 gf = unpk(Gc[(u + 64)  * G_STRIDE + cp]);
        float2 gg = unpk(Gc[(u + 128) * G_STRIDE + cp]);
        float2 go = unpk(Gc[(u + 192) * G_STRIDE + cp]);
        float2 cc = *(float2*)&C[u * 128 + c0];
        cc.x = sig_f(gf.x) * cc.x + sig_f(gi.x) * tanh_f(gg.x);
        cc.y = sig_f(gf.y) * cc.y + sig_f(gi.y) * tanh_f(gg.y);
        *(float2*)&C[u * 128 + c0] = cc;
        const int qr = hrow + (u >> 2), comp = u & 3;
        ACTf[(qr * ACT_STRIDE + c0)     * 4 + comp] = sig_f(go.x) * tanh_f(cc.x);
        ACTf[(qr * ACT_STRIDE + c0 + 1) * 4 + comp] = sig_f(go.y) * tanh_f(cc.y);
    }
}

__device__ __forceinline__ void load_weights(
    const float* __restrict__ Wih0, const float* __restrict__ Whh0, const float* __restrict__ b0v,
    const float* __restrict__ Wih1, const float* __restrict__ Whh1, const float* __restrict__ b1v,
    const float* __restrict__ W_in, const float* __restrict__ b_in,
    int rr, int kh, ull* w0, ull* w1, ull& bias02, ull& bias12)
{
    const ull* hh0 = (const ull*)Whh0 + (size_t)rr * 32;
    if (kh == 0) {
        float x0 = 0.f, x1 = 0.f, x2 = 0.f, x3 = 0.f, bb = b0v[rr];
#pragma unroll
        for (int m = 0; m < 16; ++m) {
            float wm = Wih0[rr * 16 + m];
            x0 += wm * W_in[m*4+0]; x1 += wm * W_in[m*4+1];
            x2 += wm * W_in[m*4+2]; x3 += wm * W_in[m*4+3];
            bb += wm * b_in[m];
        }
        w0[0] = packf2(x0, x1); w0[1] = packf2(x2, x3);
#pragma unroll
        for (int j = 0; j < 16; ++j) w0[2 + j] = hh0[j];
        bias02 = packf2(bb, bb);
        float bv = b1v[rr];
        bias12 = packf2(bv, bv);
    } else {
#pragma unroll
        for (int j = 0; j < 16; ++j) w0[j] = hh0[16 + j];
        w0[16] = 0ull; w0[17] = 0ull;
        bias02 = 0ull; bias12 = 0ull;
    }
    const ull* c1 = (const ull*)(kh ? Whh1 : Wih1) + (size_t)rr * 32;
#pragma unroll
    for (int j = 0; j < 32; ++j) w1[j] = c1[j];
}

// One timestep: cell0/cell1 pipelined over 5 phase iterations (32 cols each).
__device__ __forceinline__ void run_step(
    const ull* __restrict__ w0, const ull* __restrict__ w1, ull bias02, ull bias12,
    float* __restrict__ sm, int tid, int rr, int kh)
{
    float4* ACT4 = (float4*)sm;
    const float4* base0 = ACT4 + (kh ? 9 : 0) * ACT_STRIDE;
    const float4* base1 = ACT4 + (kh ? ROW_H2 : ROW_H1) * ACT_STRIDE;
    ull* G0 = (ull*)(sm + OFF_G0);
    ull* G1 = (ull*)(sm + OFF_G1);
    float* C1 = sm + OFF_C1;
    float* C2 = sm + OFF_C2;

#pragma unroll 1
    for (int p = 0; p < 5; ++p) {
        if (p < 4) gate_pass<9> (base0, w0, bias02, G0, rr, kh, 32 * p);
        if (p > 0) gate_pass<16>(base1, w1, bias12, G1, rr, kh, 32 * (p - 1));
        __syncthreads();
        if (p < 4) combine_cell(G0, C1, sm, ROW_H1, tid, 32 * p);
        if (p > 0) combine_cell(G1, C2, sm, ROW_H2, tid, 32 * (p - 1));
        __syncthreads();
    }
}

__global__ void __launch_bounds__(512, 1)
lstm_seq2seq_kernel(
    const float4* __restrict__ src4,   const float4* __restrict__ trg4,
    const float*  __restrict__ W_in,   const float*  __restrict__ b_in,
    const float*  __restrict__ eWih0,  const float*  __restrict__ eWhh0, const float* __restrict__ eb0,
    const float*  __restrict__ eWih1,  const float*  __restrict__ eWhh1, const float* __restrict__ eb1,
    const float*  __restrict__ dWih0,  const float*  __restrict__ dWhh0, const float* __restrict__ db0,
    const float*  __restrict__ dWih1,  const float*  __restrict__ dWhh1, const float* __restrict__ db1,
    const float*  __restrict__ W_out,  const float*  __restrict__ b_out,
    float4*       __restrict__ out4)
{
    extern __shared__ float sm[];
    float4* ACT4 = (float4*)sm;
    const int tid  = threadIdx.x;
    const int lane = tid & 31;
    const int kh   = lane >> 4;
    const int rr   = (tid >> 5) * 16 + (lane & 15);   // gate row 0..255

    if (tid < 256) sm[OFF_WOUT + tid] = W_out[tid];
    if (tid < 4)   sm[OFF_BOUT + tid] = b_out[tid];
    // zero ACT rows 1..33 (H1, ZERO row, H2 incl pads) and C1, C2
    for (int i = tid; i < 33 * ACT_STRIDE * 4; i += 512) sm[OFF_ACT + ACT_STRIDE * 4 + i] = 0.f;
    for (int i = tid; i < 16384; i += 512) sm[OFF_C1 + i] = 0.f;
    __syncthreads();

    ull w0[18], w1[32];
    ull bias02, bias12;
    load_weights(eWih0, eWhh0, eb0, eWih1, eWhh1, eb1, W_in, b_in,
                 rr, kh, w0, w1, bias02, bias12);

    const size_t bg = (size_t)blockIdx.x * 128 + (tid & 127);

    // ================= ENCODER =================
    float4 xc, xn;
    if (tid < 128) xc = __ldg(src4 + bg * SEQ);
    for (int t = 0; t < SEQ; ++t) {
        if (tid < 128) {
            ACT4[tid] = xc;                       // X row 0
            if (t + 1 < SEQ) xn = __ldg(src4 + bg * SEQ + t + 1);
        }
        __syncthreads();
        run_step(w0, w1, bias02, bias12, sm, tid, rr, kh);
        xc = xn;
    }

    // reload decoder weights
    load_weights(dWih0, dWhh0, db0, dWih1, dWhh1, db1, W_in, b_in,
                 rr, kh, w0, w1, bias02, bias12);

    if (tid < 128) ACT4[tid] = __ldg(trg4 + bg * SEQ);  // x0 = trg[:,0]
    __syncthreads();

    // ================= DECODER =================
    for (int t = 0; t < SEQ; ++t) {
        float4 tg;
        if (tid < 128) tg = __ldg(trg4 + bg * SEQ + t);
        run_step(w0, w1, bias02, bias12, sm, tid, rr, kh);
        if (tid < 128) {
            const float* WOUT = sm + OFF_WOUT;
            float p0 = sm[OFF_BOUT+0], p1 = sm[OFF_BOUT+1], p2 = sm[OFF_BOUT+2], p3 = sm[OFF_BOUT+3];
#pragma unroll
            for (int q = 0; q < 16; ++q) {
                float4 h = ACT4[(ROW_H2 + q) * ACT_STRIDE + tid];
                p0 += WOUT[0*64+q*4]*h.x + WOUT[0*64+q*4+1]*h.y + WOUT[0*64+q*4+2]*h.z + WOUT[0*64+q*4+3]*h.w;
                p1 += WOUT[1*64+q*4]*h.x + WOUT[1*64+q*4+1]*h.y + WOUT[1*64+q*4+2]*h.z + WOUT[1*64+q*4+3]*h.w;
                p2 += WOUT[2*64+q*4]*h.x + WOUT[2*64+q*4+1]*h.y + WOUT[2*64+q*4+2]*h.z + WOUT[2*64+q*4+3]*h.w;
                p3 += WOUT[3*64+q*4]*h.x + WOUT[3*64+q*4+1]*h.y + WOUT[3*64+q*4+2]*h.z + WOUT[3*64+q*4+3]*h.w;
            }
            float4 xo;
            xo.x = p0 + tg.x; xo.y = p1 + tg.y; xo.z = p2 + tg.z; xo.w = p3 + tg.w;
            out4[bg * SEQ + t] = xo;
            ACT4[tid] = xo;                       // next X
        }
        __syncthreads();
    }
}

extern "C" void kernel_launch(void* const* d_in, const int* in_sizes, int n_in,
                              void* d_out, int out_size)
{
    (void)in_sizes; (void)n_in; (void)out_size;
    const float4* src   = (const float4*)d_in[0];
    const float4* trg   = (const float4*)d_in[1];
    const float*  W_in  = (const float*)d_in[2];
    const float*  b_in  = (const float*)d_in[3];
    const float*  eWih0 = (const float*)d_in[4];
    const float*  eWhh0 = (const float*)d_in[5];
    const float*  eb0   = (const float*)d_in[6];
    const float*  eWih1 = (const float*)d_in[7];
    const float*  eWhh1 = (const float*)d_in[8];
    const float*  eb1   = (const float*)d_in[9];
    const float*  dWih0 = (const float*)d_in[10];
    const float*  dWhh0 = (const float*)d_in[11];
    const float*  db0   = (const float*)d_in[12];
    const float*  dWih1 = (const float*)d_in[13];
    const float*  dWhh1 = (const float*)d_in[14];
    const float*  db1   = (const float*)d_in[15];
    const float*  W_out = (const float*)d_in[16];
    const float*  b_out = (const float*)d_in[17];
    float4* out = (float4*)d_out;

    const size_t smem_bytes = (size_t)SMEM_FLOATS * sizeof(float); // 206,384 B
    cudaFuncSetAttribute(lstm_seq2seq_kernel,
                         cudaFuncAttributeMaxDynamicSharedMemorySize, (int)smem_bytes);

    lstm_seq2seq_kernel<<<128, 512, smem_bytes>>>(
        src, trg, W_in, b_in,
        eWih0, eWhh0, eb0, eWih1, eWhh1, eb1,
        dWih0, dWhh0, db0, dWih1, dWhh1, db1,
        W_out, b_out, out);
}

// round 12
// speedup vs baseline: 1.0934x; 1.0004x over previous
#include <cuda_runtime.h>

// LSTM seq2seq: B=16384, S=T=64, I=4, M=16, H=64
// 128 CTAs x 512 threads (16 warps/SM). Thread = 1 gate row x half-K.
// W_in folded into cell0 (gates0 = (Wih0@W_in)@x + Whh0@h1 + b0 + Wih0@b_in).
// k-half partners = lanes l, l^16 -> shuffle reduction. Col-pair gate loop.
// Activation quad rows padded to 129 float4 so the two half-warp broadcast
// addresses never bank-conflict.

#define SEQ 64
typedef unsigned long long ull;

__device__ __forceinline__ void fma2(ull& d, ull a, ull b) {
    asm("fma.rn.f32x2 %0, %1, %2, %0;" : "+l"(d) : "l"(a), "l"(b));
}
__device__ __forceinline__ ull addf2(ull a, ull b) {
    ull r; asm("add.rn.f32x2 %0, %1, %2;" : "=l"(r) : "l"(a), "l"(b)); return r;
}
__device__ __forceinline__ float2 unpk(ull v) {
    float2 r; asm("mov.b64 {%0,%1}, %2;" : "=f"(r.x), "=f"(r.y) : "l"(v)); return r;
}
__device__ __forceinline__ ull packf2(float x, float y) {
    ull r; asm("mov.b64 %0, {%1,%2};" : "=l"(r) : "f"(x), "f"(y)); return r;
}
__device__ __forceinline__ float fexp2a(float x) { float y; asm("ex2.approx.f32 %0, %1;" : "=f"(y) : "f"(x)); return y; }
__device__ __forceinline__ float frcpa (float x) { float y; asm("rcp.approx.f32 %0, %1;" : "=f"(y) : "f"(x)); return y; }
__device__ __forceinline__ float sig_f (float x) { return frcpa(1.0f + fexp2a(-1.4426950408889634f * x)); }
__device__ __forceinline__ float tanh_f(float x) { return 2.0f * frcpa(1.0f + fexp2a(-2.8853900817779268f * x)) - 1.0f; }

// ACT: 34 quad rows x 129 float4 (stride pad). row0=X, rows1..16=H1, row17=ZERO, rows18..33=H2
#define ACT_STRIDE 129
#define ROW_X     0
#define ROW_H1    1
#define ROW_ZERO  17
#define ROW_H2    18
// smem float offsets
#define OFF_ACT   0                       // 34*129*4 = 17544 floats
#define OFF_C1    17544                   // 64x128 = 8192
#define OFF_C2    25736                   // 8192
#define OFF_G0    33928                   // 256 rows x 17 ull = 8704 floats
#define OFF_G1    42632                   // 8704
#define OFF_WOUT  51336                   // 256
#define OFF_BOUT  51592                   // 4
#define SMEM_FLOATS 51596                 // 206,384 B
#define G_STRIDE  17                      // ull per gate row

// Gate pass: thread computes row rr over its k-half for 32 cols (16 col-pairs).
template<int NQ>
__device__ __forceinline__ void gate_pass(
    const float4* __restrict__ base, const ull* __restrict__ w, ull bias2,
    ull* __restrict__ Gc, int rr, int kh, int bbase)
{
#pragma unroll 1
    for (int cp = 0; cp < 16; ++cp) {
        const int b = bbase + 2 * cp;
        ull a0x = 0ull, a0y = 0ull, a1x = 0ull, a1y = 0ull;
#pragma unroll
        for (int q = 0; q < NQ; ++q) {
            ulonglong2 v0 = *(const ulonglong2*)(base + q * ACT_STRIDE + b);
            ulonglong2 v1 = *(const ulonglong2*)(base + q * ACT_STRIDE + b + 1);
            fma2(a0x, w[2*q],   v0.x);
            fma2(a0y, w[2*q+1], v0.y);
            fma2(a1x, w[2*q],   v1.x);
            fma2(a1y, w[2*q+1], v1.y);
        }
        float2 s0 = unpk(addf2(a0x, a0y));
        float2 s1 = unpk(addf2(a1x, a1y));
        ull mine = packf2(s0.x + s0.y, s1.x + s1.y);
        ull tot  = addf2(mine, __shfl_xor_sync(0xffffffffu, mine, 16));
        if (kh == 0) Gc[rr * G_STRIDE + cp] = addf2(tot, bias2);
    }
}

// Combine one cell for 32 cols: thread = 2 units x 1 col-pair (512 items).
__device__ __forceinline__ void combine_cell(
    const ull* __restrict__ Gc, float* __restrict__ C, float* __restrict__ ACTf,
    int hrow, int tid, int bbase)
{
    const int u2 = tid >> 4;          // 0..31
    const int cp = tid & 15;
    const int c0 = bbase + 2 * cp;
#pragma unroll
    for (int j = 0; j < 2; ++j) {
        const int u = u2 * 2 + j;
        float2 gi = unpk(Gc[u * G_STRIDE + cp]);
        float2 gf = unpk(Gc[(u + 64)  * G_STRIDE + cp]);
        float2 gg = unpk(Gc[(u + 128) * G_STRIDE + cp]);
        float2 go = unpk(Gc[(u + 192) * G_STRIDE + cp]);
        float2 cc = *(float2*)&C[u * 128 + c0];
        cc.x = sig_f(gf.x) * cc.x + sig_f(gi.x) * tanh_f(gg.x);
        cc.y = sig_f(gf.y) * cc.y + sig_f(gi.y) * tanh_f(gg.y);
        *(float2*)&C[u * 128 + c0] = cc;
        const int qr = hrow + (u >> 2), comp = u & 3;
        ACTf[(qr * ACT_STRIDE + c0)     * 4 + comp] = sig_f(go.x) * tanh_f(cc.x);
        ACTf[(qr * ACT_STRIDE + c0 + 1) * 4 + comp] = sig_f(go.y) * tanh_f(cc.y);
    }
}

__device__ __forceinline__ void load_weights(
    const float* __restrict__ Wih0, const float* __restrict__ Whh0, const float* __restrict__ b0v,
    const float* __restrict__ Wih1, const float* __restrict__ Whh1, const float* __restrict__ b1v,
    const float* __restrict__ W_in, const float* __restrict__ b_in,
    int rr, int kh, ull* w0, ull* w1, ull& bias02, ull& bias12)
{
    const ull* hh0 = (const ull*)Whh0 + (size_t)rr * 32;
    if (kh == 0) {
        float x0 = 0.f, x1 = 0.f, x2 = 0.f, x3 = 0.f, bb = b0v[rr];
#pragma unroll
        for (int m = 0; m < 16; ++m) {
            float wm = Wih0[rr * 16 + m];
            x0 += wm * W_in[m*4+0]; x1 += wm * W_in[m*4+1];
            x2 += wm * W_in[m*4+2]; x3 += wm * W_in[m*4+3];
            bb += wm * b_in[m];
        }
        w0[0] = packf2(x0, x1); w0[1] = packf2(x2, x3);
#pragma unroll
        for (int j = 0; j < 16; ++j) w0[2 + j] = hh0[j];
        bias02 = packf2(bb, bb);
        float bv = b1v[rr];
        bias12 = packf2(bv, bv);
    } else {
#pragma unroll
        for (int j = 0; j < 16; ++j) w0[j] = hh0[16 + j];
        w0[16] = 0ull; w0[17] = 0ull;
        bias02 = 0ull; bias12 = 0ull;
    }
    const ull* c1 = (const ull*)(kh ? Whh1 : Wih1) + (size_t)rr * 32;
#pragma unroll
    for (int j = 0; j < 32; ++j) w1[j] = c1[j];
}

// One timestep: cell0/cell1 pipelined over 5 phase iterations (32 cols each).
__device__ __forceinline__ void run_step(
    const ull* __restrict__ w0, const ull* __restrict__ w1, ull bias02, ull bias12,
    float* __restrict__ sm, int tid, int rr, int kh)
{
    float4* ACT4 = (float4*)sm;
    const float4* base0 = ACT4 + (kh ? 9 : 0) * ACT_STRIDE;
    const float4* base1 = ACT4 + (kh ? ROW_H2 : ROW_H1) * ACT_STRIDE;
    ull* G0 = (ull*)(sm + OFF_G0);
    ull* G1 = (ull*)(sm + OFF_G1);
    float* C1 = sm + OFF_C1;
    float* C2 = sm + OFF_C2;

#pragma unroll 1
    for (int p = 0; p < 5; ++p) {
        if (p < 4) gate_pass<9> (base0, w0, bias02, G0, rr, kh, 32 * p);
        if (p > 0) gate_pass<16>(base1, w1, bias12, G1, rr, kh, 32 * (p - 1));
        __syncthreads();
        if (p < 4) combine_cell(G0, C1, sm, ROW_H1, tid, 32 * p);
        if (p > 0) combine_cell(G1, C2, sm, ROW_H2, tid, 32 * (p - 1));
        __syncthreads();
    }
}

__global__ void __launch_bounds__(512, 1)
lstm_seq2seq_kernel(
    const float4* __restrict__ src4,   const float4* __restrict__ trg4,
    const float*  __restrict__ W_in,   const float*  __restrict__ b_in,
    const float*  __restrict__ eWih0,  const float*  __restrict__ eWhh0, const float* __restrict__ eb0,
    const float*  __restrict__ eWih1,  const float*  __restrict__ eWhh1, const float* __restrict__ eb1,
    const float*  __restrict__ dWih0,  const float*  __restrict__ dWhh0, const float* __restrict__ db0,
    const float*  __restrict__ dWih1,  const float*  __restrict__ dWhh1, const float* __restrict__ db1,
    const float*  __restrict__ W_out,  const float*  __restrict__ b_out,
    float4*       __restrict__ out4)
{
    extern __shared__ float sm[];
    float4* ACT4 = (float4*)sm;
    const int tid  = threadIdx.x;
    const int lane = tid & 31;
    const int kh   = lane >> 4;
    const int rr   = (tid >> 5) * 16 + (lane & 15);   // gate row 0..255

    if (tid < 256) sm[OFF_WOUT + tid] = W_out[tid];
    if (tid < 4)   sm[OFF_BOUT + tid] = b_out[tid];
    // zero ACT rows 1..33 (H1, ZERO row, H2 incl pads) and C1, C2
    for (int i = tid; i < 33 * ACT_STRIDE * 4; i += 512) sm[OFF_ACT + ACT_STRIDE * 4 + i] = 0.f;
    for (int i = tid; i < 16384; i += 512) sm[OFF_C1 + i] = 0.f;
    __syncthreads();

    ull w0[18], w1[32];
    ull bias02, bias12;
    load_weights(eWih0, eWhh0, eb0, eWih1, eWhh1, eb1, W_in, b_in,
                 rr, kh, w0, w1, bias02, bias12);

    const size_t bg = (size_t)blockIdx.x * 128 + (tid & 127);

    // ================= ENCODER =================
    float4 xc, xn;
    if (tid < 128) xc = __ldg(src4 + bg * SEQ);
    for (int t = 0; t < SEQ; ++t) {
        if (tid < 128) {
            ACT4[tid] = xc;                       // X row 0
            if (t + 1 < SEQ) xn = __ldg(src4 + bg * SEQ + t + 1);
        }
        __syncthreads();
        run_step(w0, w1, bias02, bias12, sm, tid, rr, kh);
        xc = xn;
    }

    // reload decoder weights
    load_weights(dWih0, dWhh0, db0, dWih1, dWhh1, db1, W_in, b_in,
                 rr, kh, w0, w1, bias02, bias12);

    if (tid < 128) ACT4[tid] = __ldg(trg4 + bg * SEQ);  // x0 = trg[:,0]
    __syncthreads();

    // ================= DECODER =================
    for (int t = 0; t < SEQ; ++t) {
        float4 tg;
        if (tid < 128) tg = __ldg(trg4 + bg * SEQ + t);
        run_step(w0, w1, bias02, bias12, sm, tid, rr, kh);
        if (tid < 128) {
            const float* WOUT = sm + OFF_WOUT;
            float p0 = sm[OFF_BOUT+0], p1 = sm[OFF_BOUT+1], p2 = sm[OFF_BOUT+2], p3 = sm[OFF_BOUT+3];
#pragma unroll
            for (int q = 0; q < 16; ++q) {
                float4 h = ACT4[(ROW_H2 + q) * ACT_STRIDE + tid];
                p0 += WOUT[0*64+q*4]*h.x + WOUT[0*64+q*4+1]*h.y + WOUT[0*64+q*4+2]*h.z + WOUT[0*64+q*4+3]*h.w;
                p1 += WOUT[1*64+q*4]*h.x + WOUT[1*64+q*4+1]*h.y + WOUT[1*64+q*4+2]*h.z + WOUT[1*64+q*4+3]*h.w;
                p2 += WOUT[2*64+q*4]*h.x + WOUT[2*64+q*4+1]*h.y + WOUT[2*64+q*4+2]*h.z + WOUT[2*64+q*4+3]*h.w;
                p3 += WOUT[3*64+q*4]*h.x + WOUT[3*64+q*4+1]*h.y + WOUT[3*64+q*4+2]*h.z + WOUT[3*64+q*4+3]*h.w;
            }
            float4 xo;
            xo.x = p0 + tg.x; xo.y = p1 + tg.y; xo.z = p2 + tg.z; xo.w = p3 + tg.w;
            out4[bg * SEQ + t] = xo;
            ACT4[tid] = xo;                       // next X
        }
        __syncthreads();
    }
}

extern "C" void kernel_launch(void* const* d_in, const int* in_sizes, int n_in,
                              void* d_out, int out_size)
{
    (void)in_sizes; (void)n_in; (void)out_size;
    const float4* src   = (const float4*)d_in[0];
    const float4* trg   = (const float4*)d_in[1];
    const float*  W_in  = (const float*)d_in[2];
    const float*  b_in  = (const float*)d_in[3];
    const float*  eWih0 = (const float*)d_in[4];
    const float*  eWhh0 = (const float*)d_in[5];
    const float*  eb0   = (const float*)d_in[6];
    const float*  eWih1 = (const float*)d_in[7];
    const float*  eWhh1 = (const float*)d_in[8];
    const float*  eb1   = (const float*)d_in[9];
    const float*  dWih0 = (const float*)d_in[10];
    const float*  dWhh0 = (const float*)d_in[11];
    const float*  db0   = (const float*)d_in[12];
    const float*  dWih1 = (const float*)d_in[13];
    const float*  dWhh1 = (const float*)d_in[14];
    const float*  db1   = (const float*)d_in[15];
    const float*  W_out = (const float*)d_in[16];
    const float*  b_out = (const float*)d_in[17];
    float4* out = (float4*)d_out;

    const size_t smem_bytes = (size_t)SMEM_FLOATS * sizeof(float); // 206,384 B
    cudaFuncSetAttribute(lstm_seq2seq_kernel,
                         cudaFuncAttributeMaxDynamicSharedMemorySize, (int)smem_bytes);

    lstm_seq2seq_kernel<<<128, 512, smem_bytes>>>(
        src, trg, W_in, b_in,
        eWih0, eWhh0, eb0, eWih1, eWhh1, eb1,
        dWih0, dWhh0, db0, dWih1, dWhh1, db1,
        W_out, b_out, out);
}

// round 15
// speedup vs baseline: 4.8399x; 4.4265x over previous
#include <cuda_runtime.h>
#include <cstdint>

// LSTM seq2seq via mma.sync tf32 (m16n8k8/k4) tensor ops. B=16384, S=T=64, I=4, M=16, H=64.
// 128 CTAs x 256 threads (8 warps). Warp w owns units 8w..8w+7 of all 4 gate blocks.
// A (activations) smem [128][132] tf32: 0-63 h1 | 64-67 x | 68-131 h2.
// Cell0 weights (Whh0, Wih0@W_in, bias') in registers; cell1 weights smem [256][132].
// c-state entirely in registers; combine per-thread (acc layout aligns i,f,g,o per unit).

#define SEQ 64
#define ASTRIDE 132
typedef uint32_t u32;
typedef unsigned long long ull;

// smem word offsets
#define OFF_A   0            // 128*132 = 16896
#define OFF_B1  16896        // 256*132 = 33792
#define OFF_WT  50688        // 64 x float4 (W_out^T)
#define OFF_BO  50944        // 4
#define SMEM_WORDS 50948     // 203,792 bytes

__device__ __forceinline__ u32 tf32c(float v){ u32 r; asm("cvt.rna.tf32.f32 %0, %1;" : "=r"(r) : "f"(v)); return r; }
__device__ __forceinline__ float fexp2a(float x){ float y; asm("ex2.approx.f32 %0, %1;" : "=f"(y) : "f"(x)); return y; }
__device__ __forceinline__ float frcpa (float x){ float y; asm("rcp.approx.f32 %0, %1;" : "=f"(y) : "f"(x)); return y; }
__device__ __forceinline__ float sig_f (float x){ return frcpa(1.0f + fexp2a(-1.4426950408889634f * x)); }
__device__ __forceinline__ float tanh_f(float x){ return 2.0f * frcpa(1.0f + fexp2a(-2.8853900817779268f * x)) - 1.0f; }

__device__ __forceinline__ void mma8(float (&d)[4], const u32 (&a)[4], u32 b0, u32 b1){
    asm volatile("mma.sync.aligned.m16n8k8.row.col.f32.tf32.tf32.f32 "
        "{%0,%1,%2,%3}, {%4,%5,%6,%7}, {%8,%9}, {%0,%1,%2,%3};"
        : "+f"(d[0]),"+f"(d[1]),"+f"(d[2]),"+f"(d[3])
        : "r"(a[0]),"r"(a[1]),"r"(a[2]),"r"(a[3]), "r"(b0),"r"(b1));
}
__device__ __forceinline__ void mma4(float (&d)[4], u32 a0, u32 a1, u32 b0){
    asm volatile("mma.sync.aligned.m16n8k4.row.col.f32.tf32.tf32.f32 "
        "{%0,%1,%2,%3}, {%4,%5}, {%6}, {%0,%1,%2,%3};"
        : "+f"(d[0]),"+f"(d[1]),"+f"(d[2]),"+f"(d[3])
        : "r"(a0),"r"(a1), "r"(b0));
}

// Load one phase's weights: B1 into smem, cell0 fragments + biases into registers.
__device__ __forceinline__ void load_phase(
    u32* __restrict__ B1, int tid, int w, int g, int t4,
    const float* __restrict__ Wih0, const float* __restrict__ Whh0, const float* __restrict__ b0,
    const float* __restrict__ Wih1, const float* __restrict__ Whh1, const float* __restrict__ b1,
    const float* __restrict__ W_in, const float* __restrict__ b_in,
    u32 (&wB0)[4][8][2], u32 (&wBx)[4], float (&bias0)[4][2], float (&bias1)[4][2])
{
    {   // B1 row r = gate row (natural [i|f|g|o] order)
        const int r = tid;
#pragma unroll 4
        for (int k = 0; k < 64; ++k) B1[r*ASTRIDE + k] = tf32c(__ldg(Wih1 + r*64 + k));
#pragma unroll
        for (int k = 64; k < 68; ++k) B1[r*ASTRIDE + k] = 0u;
#pragma unroll 4
        for (int k = 0; k < 64; ++k) B1[r*ASTRIDE + 68 + k] = tf32c(__ldg(Whh1 + r*64 + k));
    }
#pragma unroll
    for (int gb = 0; gb < 4; ++gb) {
        const int row = gb*64 + 8*w + g;
#pragma unroll
        for (int kt = 0; kt < 8; ++kt) {
            wB0[gb][kt][0] = tf32c(__ldg(Whh0 + row*64 + kt*8 + t4));
            wB0[gb][kt][1] = tf32c(__ldg(Whh0 + row*64 + kt*8 + t4 + 4));
        }
        float wx = 0.f;
#pragma unroll
        for (int m = 0; m < 16; ++m) wx += __ldg(Wih0 + row*16 + m) * __ldg(W_in + m*4 + t4);
        wBx[gb] = tf32c(wx);
#pragma unroll
        for (int j = 0; j < 2; ++j) {
            const int ur = gb*64 + 8*w + 2*t4 + j;
            float bb = __ldg(b0 + ur);
#pragma unroll
            for (int m = 0; m < 16; ++m) bb += __ldg(Wih0 + ur*16 + m) * __ldg(b_in + m);
            bias0[gb][j] = bb;
            bias1[gb][j] = __ldg(b1 + ur);
        }
    }
}

__global__ void __launch_bounds__(256, 1)
lstm_tc_kernel(
    const float4* __restrict__ src4,  const float4* __restrict__ trg4,
    const float*  __restrict__ W_in,  const float*  __restrict__ b_in,
    const float*  __restrict__ eWih0, const float*  __restrict__ eWhh0, const float* __restrict__ eb0,
    const float*  __restrict__ eWih1, const float*  __restrict__ eWhh1, const float* __restrict__ eb1,
    const float*  __restrict__ dWih0, const float*  __restrict__ dWhh0, const float* __restrict__ db0,
    const float*  __restrict__ dWih1, const float*  __restrict__ dWhh1, const float* __restrict__ db1,
    const float*  __restrict__ W_out, const float*  __restrict__ b_out,
    float4*       __restrict__ out4)
{
    extern __shared__ float smf[];
    u32* Au = (u32*)smf + OFF_A;
    u32* B1 = (u32*)smf + OFF_B1;
    const int tid = threadIdx.x, w = tid >> 5, lane = tid & 31;
    const int g = lane >> 2, t4 = lane & 3;
    const size_t bg = (size_t)blockIdx.x * 128 + tid;   // valid when tid<128

    for (int i = tid; i < 128*ASTRIDE; i += 256) Au[i] = 0u;
    if (tid < 64) {
        float4 wt;
        wt.x = W_out[tid]; wt.y = W_out[64+tid]; wt.z = W_out[128+tid]; wt.w = W_out[192+tid];
        *(float4*)(smf + OFF_WT + tid*4) = wt;
    }
    if (tid == 0) *(float4*)(smf + OFF_BO) = *(const float4*)b_out;

    u32 wB0[4][8][2], wBx[4];
    float bias0[4][2], bias1[4][2];
    float c1s[32], c2s[32];
    alignas(8) u32 hb[32];
#pragma unroll
    for (int i = 0; i < 32; ++i) { c1s[i] = 0.f; c2s[i] = 0.f; }

    load_phase(B1, tid, w, g, t4, eWih0, eWhh0, eb0, eWih1, eWhh1, eb1, W_in, b_in,
               wB0, wBx, bias0, bias1);
    __syncthreads();
    if (tid < 128) {
        float4 xv = __ldg(src4 + bg * SEQ);
        Au[tid*ASTRIDE+64] = tf32c(xv.x); Au[tid*ASTRIDE+65] = tf32c(xv.y);
        Au[tid*ASTRIDE+66] = tf32c(xv.z); Au[tid*ASTRIDE+67] = tf32c(xv.w);
    }
    __syncthreads();

    float4 tgc = make_float4(0.f,0.f,0.f,0.f);
    const u32* Bq0 = B1 + (  0 + 8*w + g)*ASTRIDE;
    const u32* Bq1 = B1 + ( 64 + 8*w + g)*ASTRIDE;
    const u32* Bq2 = B1 + (128 + 8*w + g)*ASTRIDE;
    const u32* Bq3 = B1 + (192 + 8*w + g)*ASTRIDE;

    for (int t = 0; t < 2*SEQ; ++t) {
        if (t == SEQ) {
            load_phase(B1, tid, w, g, t4, dWih0, dWhh0, db0, dWih1, dWhh1, db1, W_in, b_in,
                       wB0, wBx, bias0, bias1);
            if (tid < 128) {
                tgc = __ldg(trg4 + bg * SEQ);
                Au[tid*ASTRIDE+64] = tf32c(tgc.x); Au[tid*ASTRIDE+65] = tf32c(tgc.y);
                Au[tid*ASTRIDE+66] = tf32c(tgc.z); Au[tid*ASTRIDE+67] = tf32c(tgc.w);
            }
            __syncthreads();
        }

        // ---------- cell0: gates = Whh0@h1 + Wx@x + bias' ----------
#pragma unroll
        for (int mt = 0; mt < 8; ++mt) {
            float acc[4][4];
#pragma unroll
            for (int gb = 0; gb < 4; ++gb) {
                acc[gb][0] = bias0[gb][0]; acc[gb][1] = bias0[gb][1];
                acc[gb][2] = bias0[gb][0]; acc[gb][3] = bias0[gb][1];
            }
            const u32* r0 = Au + (16*mt + g) * ASTRIDE;
            const u32* r1 = r0 + 8 * ASTRIDE;
            {
                u32 a0 = r0[64 + t4], a1 = r1[64 + t4];
                mma4(acc[0], a0, a1, wBx[0]); mma4(acc[1], a0, a1, wBx[1]);
                mma4(acc[2], a0, a1, wBx[2]); mma4(acc[3], a0, a1, wBx[3]);
            }
#pragma unroll
            for (int kt = 0; kt < 8; ++kt) {
                u32 a[4] = { r0[8*kt + t4], r1[8*kt + t4], r0[8*kt + t4 + 4], r1[8*kt + t4 + 4] };
                mma8(acc[0], a, wB0[0][kt][0], wB0[0][kt][1]);
                mma8(acc[1], a, wB0[1][kt][0], wB0[1][kt][1]);
                mma8(acc[2], a, wB0[2][kt][0], wB0[2][kt][1]);
                mma8(acc[3], a, wB0[3][kt][0], wB0[3][kt][1]);
            }
#pragma unroll
            for (int p = 0; p < 4; ++p) {
                float cc = c1s[mt*4 + p];
                cc = sig_f(acc[1][p]) * cc + sig_f(acc[0][p]) * tanh_f(acc[2][p]);
                c1s[mt*4 + p] = cc;
                hb[mt*4 + p] = tf32c(sig_f(acc[3][p]) * tanh_f(cc));
            }
        }
        __syncthreads();                                    // all mma0 reads done
        {
            const int cb = 8*w + 2*t4;
#pragma unroll
            for (int mt = 0; mt < 8; ++mt) {
                *(ull*)(Au + (16*mt + g    ) * ASTRIDE + cb) = *(ull*)&hb[4*mt];
                *(ull*)(Au + (16*mt + g + 8) * ASTRIDE + cb) = *(ull*)&hb[4*mt + 2];
            }
        }
        __syncthreads();                                    // h1 new visible

        // ---------- cell1: gates = Wih1@h1 + Whh1@h2 + b1 ----------
#pragma unroll
        for (int mtp = 0; mtp < 4; ++mtp) {
            float acc[2][4][4];
#pragma unroll
            for (int h = 0; h < 2; ++h)
#pragma unroll
                for (int gb = 0; gb < 4; ++gb) {
                    acc[h][gb][0] = bias1[gb][0]; acc[h][gb][1] = bias1[gb][1];
                    acc[h][gb][2] = bias1[gb][0]; acc[h][gb][3] = bias1[gb][1];
                }
            const u32* q0 = Au + (32*mtp + g) * ASTRIDE;
            const u32* q1 = q0 +  8 * ASTRIDE;
            const u32* q2 = q0 + 16 * ASTRIDE;
            const u32* q3 = q0 + 24 * ASTRIDE;
#pragma unroll
            for (int kt = 0; kt < 16; ++kt) {
                const int kc = (kt < 8) ? 8*kt : 68 + 8*(kt - 8);
                u32 aA[4] = { q0[kc + t4], q1[kc + t4], q0[kc + t4 + 4], q1[kc + t4 + 4] };
                u32 aB[4] = { q2[kc + t4], q3[kc + t4], q2[kc + t4 + 4], q3[kc + t4 + 4] };
                u32 b00 = Bq0[kc + t4], b01 = Bq0[kc + t4 + 4];
                u32 b10 = Bq1[kc + t4], b11 = Bq1[kc + t4 + 4];
                u32 b20 = Bq2[kc + t4], b21 = Bq2[kc + t4 + 4];
                u32 b30 = Bq3[kc + t4], b31 = Bq3[kc + t4 + 4];
                mma8(acc[0][0], aA, b00, b01); mma8(acc[1][0], aB, b00, b01);
                mma8(acc[0][1], aA, b10, b11); mma8(acc[1][1], aB, b10, b11);
                mma8(acc[0][2], aA, b20, b21); mma8(acc[1][2], aB, b20, b21);
                mma8(acc[0][3], aA, b30, b31); mma8(acc[1][3], aB, b30, b31);
            }
#pragma unroll
            for (int h = 0; h < 2; ++h)
#pragma unroll
                for (int p = 0; p < 4; ++p) {
                    const int idx = mtp*8 + h*4 + p;
                    float cc = c2s[idx];
                    cc = sig_f(acc[h][1][p]) * cc + sig_f(acc[h][0][p]) * tanh_f(acc[h][2][p]);
                    c2s[idx] = cc;
                    hb[idx] = tf32c(sig_f(acc[h][3][p]) * tanh_f(cc));
                }
        }
        __syncthreads();                                    // all mma1 reads done
        {
            const int cb2 = 68 + 8*w + 2*t4;
#pragma unroll
            for (int mt = 0; mt < 8; ++mt) {
                *(ull*)(Au + (16*mt + g    ) * ASTRIDE + cb2) = *(ull*)&hb[4*mt];
                *(ull*)(Au + (16*mt + g + 8) * ASTRIDE + cb2) = *(ull*)&hb[4*mt + 2];
            }
        }
        if (t < SEQ - 1 && tid < 128) {                     // encoder: x(t+1)
            float4 xv = __ldg(src4 + bg * SEQ + t + 1);
            Au[tid*ASTRIDE+64] = tf32c(xv.x); Au[tid*ASTRIDE+65] = tf32c(xv.y);
            Au[tid*ASTRIDE+66] = tf32c(xv.z); Au[tid*ASTRIDE+67] = tf32c(xv.w);
        }
        __syncthreads();                                    // h2 (+x) visible

        if (t >= SEQ) {                                     // decoder: projection + carry
            const int td = t - SEQ;
            if (tid < 128) {
                const u32* Ar = Au + tid*ASTRIDE + 68;
                const float4* WT4 = (const float4*)(smf + OFF_WT);
                float4 p = *(const float4*)(smf + OFF_BO);
#pragma unroll 8
                for (int k = 0; k < 64; ++k) {
                    float hv = __uint_as_float(Ar[k]);
                    float4 wt = WT4[k];
                    p.x = fmaf(wt.x, hv, p.x); p.y = fmaf(wt.y, hv, p.y);
                    p.z = fmaf(wt.z, hv, p.z); p.w = fmaf(wt.w, hv, p.w);
                }
                float4 xo;
                xo.x = p.x + tgc.x; xo.y = p.y + tgc.y; xo.z = p.z + tgc.z; xo.w = p.w + tgc.w;
                out4[bg * SEQ + td] = xo;
                Au[tid*ASTRIDE+64] = tf32c(xo.x); Au[tid*ASTRIDE+65] = tf32c(xo.y);
                Au[tid*ASTRIDE+66] = tf32c(xo.z); Au[tid*ASTRIDE+67] = tf32c(xo.w);
                if (td < SEQ - 1) tgc = __ldg(trg4 + bg * SEQ + td + 1);
            }
            __syncthreads();                                // x-new visible
        }
    }
}

extern "C" void kernel_launch(void* const* d_in, const int* in_sizes, int n_in,
                              void* d_out, int out_size)
{
    (void)in_sizes; (void)n_in; (void)out_size;
    const float4* src   = (const float4*)d_in[0];
    const float4* trg   = (const float4*)d_in[1];
    const float*  W_in  = (const float*)d_in[2];
    const float*  b_in  = (const float*)d_in[3];
    const float*  eWih0 = (const float*)d_in[4];
    const float*  eWhh0 = (const float*)d_in[5];
    const float*  eb0   = (const float*)d_in[6];
    const float*  eWih1 = (const float*)d_in[7];
    const float*  eWhh1 = (const float*)d_in[8];
    const float*  eb1   = (const float*)d_in[9];
    const float*  dWih0 = (const float*)d_in[10];
    const float*  dWhh0 = (const float*)d_in[11];
    const float*  db0   = (const float*)d_in[12];
    const float*  dWih1 = (const float*)d_in[13];
    const float*  dWhh1 = (const float*)d_in[14];
    const float*  db1   = (const float*)d_in[15];
    const float*  W_out = (const float*)d_in[16];
    const float*  b_out = (const float*)d_in[17];
    float4* out = (float4*)d_out;

    const size_t smem_bytes = (size_t)SMEM_WORDS * sizeof(float); // 203,792 B
    cudaFuncSetAttribute(lstm_tc_kernel,
                         cudaFuncAttributeMaxDynamicSharedMemorySize, (int)smem_bytes);

    lstm_tc_kernel<<<128, 256, smem_bytes>>>(
        src, trg, W_in, b_in,
        eWih0, eWhh0, eb0, eWih1, eWhh1, eb1,
        dWih0, dWhh0, db0, dWih1, dWhh1, db1,
        W_out, b_out, out);
}

// round 17
// speedup vs baseline: 6.9937x; 1.4450x over previous
#include <cuda_runtime.h>
#include <cstdint>

// LSTM seq2seq via mma.sync bf16 m16n8k16. B=16384, S=T=64, I=4, M=16, H=64.
// 128 CTAs x 512 threads (16 warps). Warp (wn=w&7, mh=w>>3): n-slice = units 8wn..8wn+7
// of all 4 gate blocks, m-half = batch rows 64mh..64mh+63 (4 m16-tiles).
// A  (bf16 pairs) smem u32[128][76]: 0-31 h1 | 32-33 x | 34-39 zero | 40-71 h2 | 72-75 pad
// B0 (cell0 weights) u32[256][44]: 0-31 Whh0 | 32-33 Wih0@W_in | 34-43 zero
// B1 (cell1 weights) u32[256][68]: 0-31 Wih1 | 32-63 Whh1 | 64-67 zero
// c-state f32 in registers; strides 76/44/68 = 12/12/4 mod 32 -> conflict-free LDS.

#define SEQ 64
#define AST 76
#define B0ST 44
#define B1ST 68
#define OFF_A 0
#define OFF_B0 9728
#define OFF_B1 20992
#define OFF_WT 38400
#define OFF_BO 38656
#define SMEM_WORDS 38660
typedef uint32_t u32;

__device__ __forceinline__ u32 pkbf(float lo, float hi){
    u32 r; asm("cvt.rn.bf16x2.f32 %0, %1, %2;" : "=r"(r) : "f"(hi), "f"(lo)); return r;
}
__device__ __forceinline__ float2 upbf(u32 v){
    float2 r; r.x = __uint_as_float(v << 16); r.y = __uint_as_float(v & 0xFFFF0000u); return r;
}
__device__ __forceinline__ float fexp2a(float x){ float y; asm("ex2.approx.f32 %0, %1;" : "=f"(y) : "f"(x)); return y; }
__device__ __forceinline__ float frcpa (float x){ float y; asm("rcp.approx.f32 %0, %1;" : "=f"(y) : "f"(x)); return y; }
__device__ __forceinline__ float sig_f (float x){ return frcpa(1.0f + fexp2a(-1.4426950408889634f * x)); }
__device__ __forceinline__ float tanh_f(float x){ return 2.0f * frcpa(1.0f + fexp2a(-2.8853900817779268f * x)) - 1.0f; }

__device__ __forceinline__ void mmab(float (&d)[4], const u32 (&a)[4], u32 b0, u32 b1){
    asm volatile("mma.sync.aligned.m16n8k16.row.col.f32.bf16.bf16.f32 "
        "{%0,%1,%2,%3}, {%4,%5,%6,%7}, {%8,%9}, {%0,%1,%2,%3};"
        : "+f"(d[0]),"+f"(d[1]),"+f"(d[2]),"+f"(d[3])
        : "r"(a[0]),"r"(a[1]),"r"(a[2]),"r"(a[3]), "r"(b0),"r"(b1));
}

// Load one phase's weights into smem (bf16) + per-thread biases.
__device__ void load_phase(u32* __restrict__ B0, u32* __restrict__ B1,
    int tid, int wn, int t4,
    const float* __restrict__ Wih0, const float* __restrict__ Whh0, const float* __restrict__ b0v,
    const float* __restrict__ Wih1, const float* __restrict__ Whh1, const float* __restrict__ b1v,
    const float* __restrict__ W_in, const float* __restrict__ b_in,
    float (&bias0)[4][2], float (&bias1)[4][2])
{
    const int r = tid >> 1, hf = tid & 1;
    {   // B1 row r, u32 cols [34*hf, 34*hf+34)
        const int c0 = 34 * hf;
#pragma unroll 1
        for (int c = c0; c < c0 + 34; ++c) {
            u32 v;
            if (c < 32)      v = pkbf(__ldg(Wih1 + r*64 + 2*c),      __ldg(Wih1 + r*64 + 2*c + 1));
            else if (c < 64) v = pkbf(__ldg(Whh1 + r*64 + 2*(c-32)), __ldg(Whh1 + r*64 + 2*(c-32) + 1));
            else             v = 0u;
            B1[r * B1ST + c] = v;
        }
    }
    {   // B0 row r, u32 cols [22*hf, 22*hf+22)
        const int c0 = 22 * hf;
#pragma unroll 1
        for (int c = c0; c < c0 + 22; ++c) {
            u32 v;
            if (c < 32) v = pkbf(__ldg(Whh0 + r*64 + 2*c), __ldg(Whh0 + r*64 + 2*c + 1));
            else if (c < 34) {
                const int j = 2 * (c - 32);
                float w0 = 0.f, w1 = 0.f;
#pragma unroll
                for (int m = 0; m < 16; ++m) {
                    float wm = __ldg(Wih0 + r*16 + m);
                    w0 += wm * __ldg(W_in + m*4 + j);
                    w1 += wm * __ldg(W_in + m*4 + j + 1);
                }
                v = pkbf(w0, w1);
            } else v = 0u;
            B0[r * B0ST + c] = v;
        }
    }
#pragma unroll
    for (int gb = 0; gb < 4; ++gb)
#pragma unroll
        for (int j = 0; j < 2; ++j) {
            const int ur = gb*64 + 8*wn + 2*t4 + j;
            float bb = __ldg(b0v + ur);
#pragma unroll
            for (int m = 0; m < 16; ++m)
                bb += __ldg(Wih0 + ur*16 + m) * __ldg(b_in + m);
            bias0[gb][j] = bb;
            bias1[gb][j] = __ldg(b1v + ur);
        }
}

__global__ void __launch_bounds__(512, 1)
lstm_bf16_kernel(
    const float4* __restrict__ src4,  const float4* __restrict__ trg4,
    const float*  __restrict__ W_in,  const float*  __restrict__ b_in,
    const float*  __restrict__ eWih0, const float*  __restrict__ eWhh0, const float* __restrict__ eb0,
    const float*  __restrict__ eWih1, const float*  __restrict__ eWhh1, const float* __restrict__ eb1,
    const float*  __restrict__ dWih0, const float*  __restrict__ dWhh0, const float* __restrict__ db0,
    const float*  __restrict__ dWih1, const float*  __restrict__ dWhh1, const float* __restrict__ db1,
    const float*  __restrict__ W_out, const float*  __restrict__ b_out,
    float4*       __restrict__ out4)
{
    extern __shared__ float smf[];
    u32* Au = (u32*)smf + OFF_A;
    u32* B0 = (u32*)smf + OFF_B0;
    u32* B1 = (u32*)smf + OFF_B1;
    const int tid = threadIdx.x, w = tid >> 5, lane = tid & 31;
    const int wn = w & 7, mh = w >> 3;
    const int g = lane >> 2, t4 = lane & 3;
    const size_t bg = (size_t)blockIdx.x * 128 + tid;   // valid when tid<128

    for (int i = tid; i < 128*AST; i += 512) Au[i] = 0u;
    if (tid < 64) {
        float4 wt;
        wt.x = W_out[tid]; wt.y = W_out[64+tid]; wt.z = W_out[128+tid]; wt.w = W_out[192+tid];
        *(float4*)(smf + OFF_WT + tid*4) = wt;
    }
    if (tid == 0) *(float4*)(smf + OFF_BO) = *(const float4*)b_out;

    float bias0[4][2], bias1[4][2];
    float c1s[16], c2s[16];
#pragma unroll
    for (int i = 0; i < 16; ++i) { c1s[i] = 0.f; c2s[i] = 0.f; }

    load_phase(B0, B1, tid, wn, t4, eWih0, eWhh0, eb0, eWih1, eWhh1, eb1, W_in, b_in, bias0, bias1);
    __syncthreads();
    if (tid < 128) {
        float4 xv = __ldg(src4 + bg * SEQ);
        Au[tid*AST+32] = pkbf(xv.x, xv.y); Au[tid*AST+33] = pkbf(xv.z, xv.w);
    }
    __syncthreads();

    const int b0r0 = (  0 + 8*wn + g)*B0ST, b0r1 = ( 64 + 8*wn + g)*B0ST,
              b0r2 = (128 + 8*wn + g)*B0ST, b0r3 = (192 + 8*wn + g)*B0ST;
    const int b1r0 = (  0 + 8*wn + g)*B1ST, b1r1 = ( 64 + 8*wn + g)*B1ST,
              b1r2 = (128 + 8*wn + g)*B1ST, b1r3 = (192 + 8*wn + g)*B1ST;
    float4 tgc = make_float4(0.f,0.f,0.f,0.f);

    for (int t = 0; t < 2*SEQ; ++t) {
        if (t == SEQ) {
            load_phase(B0, B1, tid, wn, t4, dWih0, dWhh0, db0, dWih1, dWhh1, db1, W_in, b_in, bias0, bias1);
            if (tid < 128) {
                tgc = __ldg(trg4 + bg * SEQ);
                Au[tid*AST+32] = pkbf(tgc.x, tgc.y); Au[tid*AST+33] = pkbf(tgc.z, tgc.w);
            }
            __syncthreads();
        }

        // ---------- cell0: gates = Whh0@h1 + Wx@x + bias' (5 k16-tiles) ----------
        u32 hb0[8];
#pragma unroll
        for (int lmt = 0; lmt < 4; ++lmt) {
            const int mt = 4*mh + lmt;
            float acc[4][4];
#pragma unroll
            for (int gb = 0; gb < 4; ++gb) {
                acc[gb][0] = bias0[gb][0]; acc[gb][1] = bias0[gb][1];
                acc[gb][2] = bias0[gb][0]; acc[gb][3] = bias0[gb][1];
            }
            const u32* r0 = Au + (16*mt + g) * AST;
            const u32* r1 = r0 + 8 * AST;
#pragma unroll
            for (int kt = 0; kt < 5; ++kt) {
                const int kb = 8*kt;
                u32 a[4] = { r0[kb+t4], r1[kb+t4], r0[kb+t4+4], r1[kb+t4+4] };
                mmab(acc[0], a, B0[b0r0+kb+t4], B0[b0r0+kb+t4+4]);
                mmab(acc[1], a, B0[b0r1+kb+t4], B0[b0r1+kb+t4+4]);
                mmab(acc[2], a, B0[b0r2+kb+t4], B0[b0r2+kb+t4+4]);
                mmab(acc[3], a, B0[b0r3+kb+t4], B0[b0r3+kb+t4+4]);
            }
            float hv[4];
#pragma unroll
            for (int p = 0; p < 4; ++p) {
                float cc = c1s[lmt*4 + p];
                cc = sig_f(acc[1][p]) * cc + sig_f(acc[0][p]) * tanh_f(acc[2][p]);
                c1s[lmt*4 + p] = cc;
                hv[p] = sig_f(acc[3][p]) * tanh_f(cc);
            }
            hb0[2*lmt]   = pkbf(hv[0], hv[1]);
            hb0[2*lmt+1] = pkbf(hv[2], hv[3]);
        }
        __syncthreads();                                 // old h1/x reads done
#pragma unroll
        for (int lmt = 0; lmt < 4; ++lmt) {
            const int row = 16*(4*mh + lmt) + g;
            Au[row*AST + 4*wn + t4]     = hb0[2*lmt];
            Au[(row+8)*AST + 4*wn + t4] = hb0[2*lmt+1];
        }
        __syncthreads();                                 // new h1 visible

        // ---------- cell1: gates = Wih1@h1 + Whh1@h2 + b1 (8 k16-tiles) ----------
        u32 hb1[8];
#pragma unroll
        for (int i = 0; i < 2; ++i) {
            const int base = 64*mh + 32*i;
            float acc[2][4][4];
#pragma unroll
            for (int h = 0; h < 2; ++h)
#pragma unroll
                for (int gb = 0; gb < 4; ++gb) {
                    acc[h][gb][0] = bias1[gb][0]; acc[h][gb][1] = bias1[gb][1];
                    acc[h][gb][2] = bias1[gb][0]; acc[h][gb][3] = bias1[gb][1];
                }
            const u32* q0 = Au + (base + g) * AST;
            const u32* q1 = q0 +  8 * AST;
            const u32* q2 = q0 + 16 * AST;
            const u32* q3 = q0 + 24 * AST;
#pragma unroll
            for (int kt = 0; kt < 8; ++kt) {
                const int ka = (kt < 4) ? 8*kt : 40 + 8*(kt-4);
                const int kb = 8*kt;
                u32 aA[4] = { q0[ka+t4], q1[ka+t4], q0[ka+t4+4], q1[ka+t4+4] };
                u32 aB[4] = { q2[ka+t4], q3[ka+t4], q2[ka+t4+4], q3[ka+t4+4] };
                u32 b00 = B1[b1r0+kb+t4], b01 = B1[b1r0+kb+t4+4];
                u32 b10 = B1[b1r1+kb+t4], b11 = B1[b1r1+kb+t4+4];
                u32 b20 = B1[b1r2+kb+t4], b21 = B1[b1r2+kb+t4+4];
                u32 b30 = B1[b1r3+kb+t4], b31 = B1[b1r3+kb+t4+4];
                mmab(acc[0][0], aA, b00, b01); mmab(acc[1][0], aB, b00, b01);
                mmab(acc[0][1], aA, b10, b11); mmab(acc[1][1], aB, b10, b11);
                mmab(acc[0][2], aA, b20, b21); mmab(acc[1][2], aB, b20, b21);
                mmab(acc[0][3], aA, b30, b31); mmab(acc[1][3], aB, b30, b31);
            }
#pragma unroll
            for (int h = 0; h < 2; ++h) {
                float hv[4];
#pragma unroll
                for (int p = 0; p < 4; ++p) {
                    const int idx = (2*i + h)*4 + p;
                    float cc = c2s[idx];
                    cc = sig_f(acc[h][1][p]) * cc + sig_f(acc[h][0][p]) * tanh_f(acc[h][2][p]);
                    c2s[idx] = cc;
                    hv[p] = sig_f(acc[h][3][p]) * tanh_f(cc);
                }
                hb1[(2*i+h)*2]   = pkbf(hv[0], hv[1]);
                hb1[(2*i+h)*2+1] = pkbf(hv[2], hv[3]);
            }
        }
        __syncthreads();                                 // old h2 reads done
#pragma unroll
        for (int j = 0; j < 4; ++j) {
            const int row = 16*(4*mh + j) + g;
            Au[row*AST + 40 + 4*wn + t4]     = hb1[2*j];
            Au[(row+8)*AST + 40 + 4*wn + t4] = hb1[2*j+1];
        }
        if (t < SEQ - 1 && tid < 128) {                  // encoder x(t+1)
            float4 xv = __ldg(src4 + bg * SEQ + t + 1);
            Au[tid*AST+32] = pkbf(xv.x, xv.y); Au[tid*AST+33] = pkbf(xv.z, xv.w);
        }
        __syncthreads();                                 // h2 (+x) visible

        if (t >= SEQ) {                                  // decoder projection + feedback
            const int td = t - SEQ;
            if (tid < 128) {
                const u32* Ar = Au + tid*AST + 40;
                const float4* WT4 = (const float4*)(smf + OFF_WT);
                float4 p = *(const float4*)(smf + OFF_BO);
#pragma unroll 8
                for (int k = 0; k < 32; ++k) {
                    float2 hv = upbf(Ar[k]);
                    float4 w0 = WT4[2*k], w1 = WT4[2*k+1];
                    p.x = fmaf(w0.x, hv.x, fmaf(w1.x, hv.y, p.x));
                    p.y = fmaf(w0.y, hv.x, fmaf(w1.y, hv.y, p.y));
                    p.z = fmaf(w0.z, hv.x, fmaf(w1.z, hv.y, p.z));
                    p.w = fmaf(w0.w, hv.x, fmaf(w1.w, hv.y, p.w));
                }
                float4 xo;
                xo.x = p.x + tgc.x; xo.y = p.y + tgc.y; xo.z = p.z + tgc.z; xo.w = p.w + tgc.w;
                out4[bg * SEQ + td] = xo;
                Au[tid*AST+32] = pkbf(xo.x, xo.y); Au[tid*AST+33] = pkbf(xo.z, xo.w);
                if (td < SEQ - 1) tgc = __ldg(trg4 + bg * SEQ + td + 1);
            }
            __syncthreads();                             // x-new visible
        }
    }
}

extern "C" void kernel_launch(void* const* d_in, const int* in_sizes, int n_in,
                              void* d_out, int out_size)
{
    (void)in_sizes; (void)n_in; (void)out_size;
    const float4* src   = (const float4*)d_in[0];
    const float4* trg   = (const float4*)d_in[1];
    const float*  W_in  = (const float*)d_in[2];
    const float*  b_in  = (const float*)d_in[3];
    const float*  eWih0 = (const float*)d_in[4];
    const float*  eWhh0 = (const float*)d_in[5];
    const float*  eb0   = (const float*)d_in[6];
    const float*  eWih1 = (const float*)d_in[7];
    const float*  eWhh1 = (const float*)d_in[8];
    const float*  eb1   = (const float*)d_in[9];
    const float*  dWih0 = (const float*)d_in[10];
    const float*  dWhh0 = (const float*)d_in[11];
    const float*  db0   = (const float*)d_in[12];
    const float*  dWih1 = (const float*)d_in[13];
    const float*  dWhh1 = (const float*)d_in[14];
    const float*  db1   = (const float*)d_in[15];
    const float*  W_out = (const float*)d_in[16];
    const float*  b_out = (const float*)d_in[17];
    float4* out = (float4*)d_out;

    const size_t smem_bytes = (size_t)SMEM_WORDS * sizeof(float); // 154,640 B
    cudaFuncSetAttribute(lstm_bf16_kernel,
                         cudaFuncAttributeMaxDynamicSharedMemorySize, (int)smem_bytes);

    lstm_bf16_kernel<<<128, 512, smem_bytes>>>(
        src, trg, W_in, b_in,
        eWih0, eWhh0, eb0, eWih1, eWhh1, eb1,
        dWih0, dWhh0, db0, dWih1, dWhh1, db1,
        W_out, b_out, out);
}